// round 6
// baseline (speedup 1.0000x reference)
#include <cuda_runtime.h>
#include <cuda_bf16.h>

// Problem constants (fixed by reference setup_inputs)
#define BATCH   16
#define NHEAD   16
#define HDIM    64
#define HW      4096                   // H*W
#define NROWS   (BATCH * NHEAD * HDIM) // 16384 rows of 4096 floats
#define LSEQ    16                     // sequence length (= nH)
#define BN      4                      // bottleneck dim
#define MHA_H   2
#define DH      2

#define GRID    1024                   // one block per row of the current batch
#define TPB     128

// Scratch + barrier state (no allocations allowed)
__device__ float    g_pooled[NROWS];
__device__ unsigned g_bar_count = 0;
__device__ unsigned g_bar_sense = 0;   // monotonically increasing epoch

__global__ __launch_bounds__(TPB, 8) void fused_kernel(
    const float* __restrict__ x,   float* __restrict__ out,
    const float* __restrict__ cw,  const float* __restrict__ cb,
    const float* __restrict__ ipw, const float* __restrict__ ipb,
    const float* __restrict__ opw, const float* __restrict__ opb,
    const float* __restrict__ ew,  const float* __restrict__ eb,
    const float* __restrict__ lnw, const float* __restrict__ lnb,
    const float* __restrict__ gate)
{
    const int bid   = blockIdx.x;      // row within batch: nH*64 + hd
    const int t     = threadIdx.x;
    const int my_nH = bid >> 6;
    const int my_hd = bid & 63;

    // --- shared memory ---------------------------------------------------
    __shared__ float sp     [LSEQ][HDIM];   // pooled for current batch
    __shared__ float s_xc   [LSEQ][BN];
    __shared__ float s_qkv  [LSEQ][3 * BN];
    __shared__ float s_sc   [MHA_H * LSEQ][LSEQ];  // attention scores
    __shared__ float s_ov   [LSEQ][BN];
    __shared__ float s_xat  [LSEQ][BN];
    __shared__ float s_delta[HDIM];         // delta for my_nH
    __shared__ float wred[2];
    __shared__ float ws[4];
    __shared__ unsigned s_e0;
    // weights
    __shared__ float s_cw [BN * HDIM], s_cb [BN];
    __shared__ float s_ipw[3 * BN * BN], s_ipb[3 * BN];
    __shared__ float s_opw[BN * BN],  s_opb[BN];
    __shared__ float s_ew [HDIM * BN], s_eb [HDIM];
    __shared__ float s_lnw[HDIM], s_lnb[HDIM];
    __shared__ float s_gate;

    // --- cache weights once ------------------------------------------------
    for (int i = t; i < BN * HDIM; i += TPB) s_cw[i] = cw[i];
    for (int i = t; i < HDIM * BN; i += TPB) s_ew[i] = ew[i];
    if (t < 3 * BN * BN) s_ipw[t] = ipw[t];
    if (t < 3 * BN)      s_ipb[t] = ipb[t];
    if (t < BN * BN)     s_opw[t] = opw[t];
    if (t < BN)        { s_opb[t] = opb[t]; s_cb[t] = cb[t]; }
    if (t < HDIM)      { s_eb[t] = eb[t]; s_lnw[t] = lnw[t]; s_lnb[t] = lnb[t]; }
    if (t == 0) {
        s_gate = gate[0];
        s_e0   = *(volatile unsigned*)&g_bar_sense;   // barrier epoch at entry
    }
    __syncthreads();
    const unsigned e0 = s_e0;
    const float    g  = s_gate;

    for (int b = 0; b < BATCH; b++) {
        const size_t grow = (size_t)b * (LSEQ * HDIM) + bid;
        const float4* __restrict__ xr =
            reinterpret_cast<const float4*>(x) + grow * (HW / 4);

        // ---- pool: row mean (each thread 8 float4) ------------------------
        float s = 0.f;
#pragma unroll
        for (int i = 0; i < 8; i++) {
            float4 v = xr[t + i * TPB];
            s += (v.x + v.y) + (v.z + v.w);
        }
#pragma unroll
        for (int off = 16; off; off >>= 1)
            s += __shfl_xor_sync(0xffffffffu, s, off);
        if ((t & 31) == 0) ws[t >> 5] = s;
        __syncthreads();
        if (t == 0)
            g_pooled[grow] = (ws[0] + ws[1] + ws[2] + ws[3]) * (1.0f / (float)HW);

        // ---- grid barrier (sense = epoch counter) -------------------------
        __syncthreads();
        if (t == 0) {
            __threadfence();
            const unsigned target = e0 + (unsigned)(b + 1);
            unsigned old = atomicAdd(&g_bar_count, 1u);
            if (old == GRID - 1) {
                g_bar_count = 0;
                __threadfence();
                atomicAdd(&g_bar_sense, 1u);
            } else {
                while ((int)(*(volatile unsigned*)&g_bar_sense - target) < 0)
                    __nanosleep(32);
            }
            __threadfence();
        }
        __syncthreads();

        // ---- middle (redundant per block) ---------------------------------
        const float* __restrict__ pb = g_pooled + (size_t)b * (LSEQ * HDIM);
        for (int i = t; i < LSEQ * HDIM; i += TPB)
            sp[i >> 6][i & 63] = pb[i];
        __syncthreads();

        // compress: 64 outputs
        if (t < LSEQ * BN) {
            const int l = t >> 2, e = t & 3;
            float acc = s_cb[e];
#pragma unroll
            for (int k = 0; k < HDIM; k++)
                acc = fmaf(sp[l][k], s_cw[e * HDIM + k], acc);
            s_xc[l][e] = acc;
        }
        __syncthreads();

        // qkv: 192 outputs
        for (int idx = t; idx < LSEQ * 3 * BN; idx += TPB) {
            const int l = idx / (3 * BN), e = idx % (3 * BN);
            float acc = s_ipb[e];
#pragma unroll
            for (int k = 0; k < BN; k++)
                acc = fmaf(s_xc[l][k], s_ipw[e * BN + k], acc);
            s_qkv[l][e] = acc;
        }
        __syncthreads();

        // attention: 2 heads x 16 queries (scores in smem to save registers)
        if (t < MHA_H * LSEQ) {
            const int h = t / LSEQ, q = t % LSEQ;
            const float scale = rsqrtf((float)DH);
            const float q0 = s_qkv[q][h * DH + 0];
            const float q1 = s_qkv[q][h * DH + 1];
            float m = -1e30f;
#pragma unroll
            for (int k = 0; k < LSEQ; k++) {
                float sc = (q0 * s_qkv[k][BN + h * DH + 0] +
                            q1 * s_qkv[k][BN + h * DH + 1]) * scale;
                s_sc[t][k] = sc;
                m = fmaxf(m, sc);
            }
            float den = 0.f;
#pragma unroll
            for (int k = 0; k < LSEQ; k++) {
                float e2 = __expf(s_sc[t][k] - m);
                s_sc[t][k] = e2;
                den += e2;
            }
            const float inv = 1.0f / den;
            float o0 = 0.f, o1 = 0.f;
#pragma unroll
            for (int k = 0; k < LSEQ; k++) {
                const float a = s_sc[t][k] * inv;
                o0 = fmaf(a, s_qkv[k][2 * BN + h * DH + 0], o0);
                o1 = fmaf(a, s_qkv[k][2 * BN + h * DH + 1], o1);
            }
            s_ov[q][h * DH + 0] = o0;
            s_ov[q][h * DH + 1] = o1;
        }
        __syncthreads();

        // out_proj: 64 outputs
        if (t < LSEQ * BN) {
            const int l = t >> 2, e = t & 3;
            float acc = s_opb[e];
#pragma unroll
            for (int k = 0; k < BN; k++)
                acc = fmaf(s_ov[l][k], s_opw[e * BN + k], acc);
            s_xat[l][e] = acc;
        }
        __syncthreads();

        // expand + residual + gate + LN for l = my_nH (threads 0..63)
        float y = 0.f, res = 0.f;
        if (t < HDIM) {
            float xe = s_eb[t];
#pragma unroll
            for (int k = 0; k < BN; k++)
                xe = fmaf(s_xat[my_nH][k], s_ew[t * BN + k], xe);
            res = sp[my_nH][t];
            y = fmaf(g, xe, res);
        }
        float sm = (t < HDIM) ? y : 0.f;
#pragma unroll
        for (int off = 16; off; off >>= 1)
            sm += __shfl_xor_sync(0xffffffffu, sm, off);
        if (t == 0 || t == 32) wred[t >> 5] = sm;
        __syncthreads();
        const float mu = (wred[0] + wred[1]) * (1.0f / (float)HDIM);
        __syncthreads();

        const float dy = (t < HDIM) ? (y - mu) : 0.f;
        float s2 = dy * dy;
#pragma unroll
        for (int off = 16; off; off >>= 1)
            s2 += __shfl_xor_sync(0xffffffffu, s2, off);
        if (t == 0 || t == 32) wred[t >> 5] = s2;
        __syncthreads();
        const float var = (wred[0] + wred[1]) * (1.0f / (float)HDIM);
        if (t < HDIM) {
            const float ln = dy * rsqrtf(var + 1e-5f) * s_lnw[t] + s_lnb[t];
            s_delta[t] = ln - res;
        }
        __syncthreads();

        // ---- write phase: re-read x (L2 hit) + add delta -------------------
        const float d = s_delta[my_hd];
        float4* __restrict__ orow =
            reinterpret_cast<float4*>(out) + grow * (HW / 4);
#pragma unroll
        for (int i = 0; i < 8; i++) {
            float4 v = xr[t + i * TPB];   // just read by pool phase -> L2 hit
            v.x += d; v.y += d; v.z += d; v.w += d;
            orow[t + i * TPB] = v;
        }
        // next iteration's __syncthreads (after ws store) guards smem reuse
    }
}

// ---------------------------------------------------------------------------
extern "C" void kernel_launch(void* const* d_in, const int* in_sizes, int n_in,
                              void* d_out, int out_size) {
    const float* x   = (const float*)d_in[0];
    const float* cw  = (const float*)d_in[1];
    const float* cb  = (const float*)d_in[2];
    const float* ipw = (const float*)d_in[3];
    const float* ipb = (const float*)d_in[4];
    const float* opw = (const float*)d_in[5];
    const float* opb = (const float*)d_in[6];
    const float* ew  = (const float*)d_in[7];
    const float* eb  = (const float*)d_in[8];
    const float* lnw = (const float*)d_in[9];
    const float* lnb = (const float*)d_in[10];
    const float* gt  = (const float*)d_in[11];
    float* out = (float*)d_out;

    fused_kernel<<<GRID, TPB>>>(x, out, cw, cb, ipw, ipb, opw, opb,
                                ew, eb, lnw, lnb, gt);
}

// round 7
// speedup vs baseline: 1.2361x; 1.2361x over previous
#include <cuda_runtime.h>
#include <cuda_bf16.h>

// Problem constants (fixed by reference setup_inputs)
#define BATCH   16
#define NHEAD   16
#define HDIM    64
#define HW      4096                   // H*W
#define NROWS   (BATCH * NHEAD * HDIM) // 16384 rows of 4096 floats
#define LSEQ    16                     // sequence length (= nH)
#define BN      4                      // bottleneck dim
#define MHA_H   2
#define DH      2

#define GRID    1024                   // one block per row of the current batch
#define TPB     256
#define PREFETCH 2                     // batches pooled ahead of the barrier wait

// Scratch + barrier state (no allocations allowed)
__device__ float    g_pooled[NROWS];
__device__ unsigned g_cnt[BATCH];          // per-batch arrival counters (self-resetting)
__device__ unsigned g_epoch = 0;           // monotonic release counter (16 per replay)

__global__ __launch_bounds__(TPB, 7) void fused_kernel(
    const float* __restrict__ x,   float* __restrict__ out,
    const float* __restrict__ cw,  const float* __restrict__ cb,
    const float* __restrict__ ipw, const float* __restrict__ ipb,
    const float* __restrict__ opw, const float* __restrict__ opb,
    const float* __restrict__ ew,  const float* __restrict__ eb,
    const float* __restrict__ lnw, const float* __restrict__ lnb,
    const float* __restrict__ gate)
{
    const int bid   = blockIdx.x;          // row within batch: nH*64 + hd
    const int t     = threadIdx.x;
    const int my_nH = bid >> 6;
    const int my_hd = bid & 63;

    // --- shared memory -----------------------------------------------------
    __shared__ float sp   [LSEQ * HDIM];    // pooled for current batch (1024)
    __shared__ float s_xc [LSEQ][BN];
    __shared__ float s_qkv[LSEQ][3 * BN];
    __shared__ float s_sc [MHA_H * LSEQ][LSEQ];
    __shared__ float s_ov [LSEQ][BN];
    __shared__ float s_xat[LSEQ][BN];
    __shared__ float s_dval;                 // this block's delta scalar
    __shared__ float ws[8];                  // pool reduction scratch
    __shared__ float wred[2];                // LN reduction scratch
    __shared__ unsigned s_e0;
    // weights
    __shared__ float s_cw [BN * HDIM], s_cb [BN];
    __shared__ float s_ipw[3 * BN * BN], s_ipb[3 * BN];
    __shared__ float s_opw[BN * BN],  s_opb[BN];
    __shared__ float s_ew [HDIM * BN], s_eb [HDIM];
    __shared__ float s_lnw[HDIM], s_lnb[HDIM];
    __shared__ float s_gate;

    // --- cache weights once --------------------------------------------------
    for (int i = t; i < BN * HDIM; i += TPB) s_cw[i] = cw[i];
    for (int i = t; i < HDIM * BN; i += TPB) s_ew[i] = ew[i];
    if (t < 3 * BN * BN) s_ipw[t] = ipw[t];
    if (t < 3 * BN)      s_ipb[t] = ipb[t];
    if (t < BN * BN)     s_opw[t] = opw[t];
    if (t < BN)        { s_opb[t] = opb[t]; s_cb[t] = cb[t]; }
    if (t < HDIM)      { s_eb[t] = eb[t]; s_lnw[t] = lnw[t]; s_lnb[t] = lnb[t]; }
    if (t == 0) {
        s_gate = gate[0];
        s_e0   = *(volatile unsigned*)&g_epoch;  // epoch at entry (before any arrive)
    }
    __syncthreads();
    const unsigned e0 = s_e0;
    const float    g  = s_gate;

    const float4* __restrict__ x4  = reinterpret_cast<const float4*>(x);
    float4*       __restrict__ o4  = reinterpret_cast<float4*>(out);

    // ---- pool one batch's row + arrive at its barrier -----------------------
    auto pool_and_arrive = [&](int b) {
        const size_t grow = (size_t)b * (LSEQ * HDIM) + bid;
        const float4* __restrict__ xr = x4 + grow * (HW / 4);
        float s = 0.f;
#pragma unroll
        for (int i = 0; i < 4; i++) {
            float4 v = xr[t + i * TPB];     // default policy: keep in L2
            s += (v.x + v.y) + (v.z + v.w);
        }
#pragma unroll
        for (int off = 16; off; off >>= 1)
            s += __shfl_xor_sync(0xffffffffu, s, off);
        if ((t & 31) == 0) ws[t >> 5] = s;
        __syncthreads();
        if (t == 0) {
            float tot = 0.f;
#pragma unroll
            for (int w = 0; w < 8; w++) tot += ws[w];
            g_pooled[grow] = tot * (1.0f / (float)HW);
            __threadfence();
            unsigned old = atomicAdd(&g_cnt[b], 1u);
            if (old == GRID - 1) {          // last arriver: reset + release
                g_cnt[b] = 0;
                __threadfence();
                atomicAdd(&g_epoch, 1u);
            }
        }
        __syncthreads();                     // protect ws for the next pool
    };

    // ---- prologue: prefetch PREFETCH batches -------------------------------
#pragma unroll
    for (int b = 0; b < PREFETCH; b++)
        pool_and_arrive(b);

    for (int b = 0; b < BATCH; b++) {
        // prefetch pool for batch b+PREFETCH (keeps DRAM busy during wait)
        if (b + PREFETCH < BATCH)
            pool_and_arrive(b + PREFETCH);

        // ---- wait for batch b's pools (epoch >= e0 + b + 1) ----------------
        if (t == 0) {
            const unsigned target = e0 + (unsigned)(b + 1);
            while ((int)(*(volatile unsigned*)&g_epoch - target) < 0)
                __nanosleep(32);
            __threadfence();
        }
        __syncthreads();

        // ---- middle (redundant per block, tiny) -----------------------------
        const float* __restrict__ pb = g_pooled + (size_t)b * (LSEQ * HDIM);
#pragma unroll
        for (int i = 0; i < 4; i++)
            sp[t + i * TPB] = pb[t + i * TPB];
        __syncthreads();

        // compress: 64 outputs (l,e)
        if (t < LSEQ * BN) {
            const int l = t >> 2, e = t & 3;
            float acc = s_cb[e];
#pragma unroll 8
            for (int k = 0; k < HDIM; k++)
                acc = fmaf(sp[l * HDIM + k], s_cw[e * HDIM + k], acc);
            s_xc[l][e] = acc;
        }
        __syncthreads();

        // qkv: 192 outputs
        if (t < LSEQ * 3 * BN) {
            const int l = t / (3 * BN), e = t % (3 * BN);
            float acc = s_ipb[e];
#pragma unroll
            for (int k = 0; k < BN; k++)
                acc = fmaf(s_xc[l][k], s_ipw[e * BN + k], acc);
            s_qkv[l][e] = acc;
        }
        __syncthreads();

        // attention: 2 heads x 16 queries (scores staged in smem)
        if (t < MHA_H * LSEQ) {
            const int h = t / LSEQ, q = t % LSEQ;
            const float scale = rsqrtf((float)DH);
            const float q0 = s_qkv[q][h * DH + 0];
            const float q1 = s_qkv[q][h * DH + 1];
            float m = -1e30f;
#pragma unroll
            for (int k = 0; k < LSEQ; k++) {
                float sc = (q0 * s_qkv[k][BN + h * DH + 0] +
                            q1 * s_qkv[k][BN + h * DH + 1]) * scale;
                s_sc[t][k] = sc;
                m = fmaxf(m, sc);
            }
            float den = 0.f;
#pragma unroll
            for (int k = 0; k < LSEQ; k++) {
                float e2 = __expf(s_sc[t][k] - m);
                s_sc[t][k] = e2;
                den += e2;
            }
            const float inv = 1.0f / den;
            float o0 = 0.f, o1 = 0.f;
#pragma unroll
            for (int k = 0; k < LSEQ; k++) {
                const float a = s_sc[t][k] * inv;
                o0 = fmaf(a, s_qkv[k][2 * BN + h * DH + 0], o0);
                o1 = fmaf(a, s_qkv[k][2 * BN + h * DH + 1], o1);
            }
            s_ov[q][h * DH + 0] = o0;
            s_ov[q][h * DH + 1] = o1;
        }
        __syncthreads();

        // out_proj: 64 outputs
        if (t < LSEQ * BN) {
            const int l = t >> 2, e = t & 3;
            float acc = s_opb[e];
#pragma unroll
            for (int k = 0; k < BN; k++)
                acc = fmaf(s_ov[l][k], s_opw[e * BN + k], acc);
            s_xat[l][e] = acc;
        }
        __syncthreads();

        // expand + residual + gate + LN for l = my_nH (threads 0..63)
        float y = 0.f, res = 0.f;
        if (t < HDIM) {
            float xe = s_eb[t];
#pragma unroll
            for (int k = 0; k < BN; k++)
                xe = fmaf(s_xat[my_nH][k], s_ew[t * BN + k], xe);
            res = sp[my_nH * HDIM + t];
            y = fmaf(g, xe, res);
        }
        float sm = (t < HDIM) ? y : 0.f;
#pragma unroll
        for (int off = 16; off; off >>= 1)
            sm += __shfl_xor_sync(0xffffffffu, sm, off);
        if (t == 0 || t == 32) wred[t >> 5] = sm;
        __syncthreads();
        const float mu = (wred[0] + wred[1]) * (1.0f / (float)HDIM);
        __syncthreads();

        const float dy = (t < HDIM) ? (y - mu) : 0.f;
        float s2 = dy * dy;
#pragma unroll
        for (int off = 16; off; off >>= 1)
            s2 += __shfl_xor_sync(0xffffffffu, s2, off);
        if (t == 0 || t == 32) wred[t >> 5] = s2;
        __syncthreads();
        const float var = (wred[0] + wred[1]) * (1.0f / (float)HDIM);
        if (t == my_hd) {
            const float ln = dy * rsqrtf(var + 1e-5f) * s_lnw[t] + s_lnb[t];
            s_dval = ln - res;
        }
        __syncthreads();

        // ---- write phase: re-read x (L2-resident) + add delta ---------------
        const float d = s_dval;
        const size_t grow = (size_t)b * (LSEQ * HDIM) + bid;
        const float4* __restrict__ xr = x4 + grow * (HW / 4);
        float4*       __restrict__ orow = o4 + grow * (HW / 4);
#pragma unroll
        for (int i = 0; i < 4; i++) {
            float4 v = __ldcs(xr + t + i * TPB);   // hit L2, then evict-first
            v.x += d; v.y += d; v.z += d; v.w += d;
            __stcs(orow + t + i * TPB, v);          // streaming store
        }
        // next iteration's syncthreads (inside pool) guards smem reuse
    }
}

// ---------------------------------------------------------------------------
extern "C" void kernel_launch(void* const* d_in, const int* in_sizes, int n_in,
                              void* d_out, int out_size) {
    const float* x   = (const float*)d_in[0];
    const float* cw  = (const float*)d_in[1];
    const float* cb  = (const float*)d_in[2];
    const float* ipw = (const float*)d_in[3];
    const float* ipb = (const float*)d_in[4];
    const float* opw = (const float*)d_in[5];
    const float* opb = (const float*)d_in[6];
    const float* ew  = (const float*)d_in[7];
    const float* eb  = (const float*)d_in[8];
    const float* lnw = (const float*)d_in[9];
    const float* lnb = (const float*)d_in[10];
    const float* gt  = (const float*)d_in[11];
    float* out = (float*)d_out;

    fused_kernel<<<GRID, TPB>>>(x, out, cw, cb, ipw, ipb, opw, opb,
                                ew, eb, lnw, lnb, gt);
}

// round 8
// speedup vs baseline: 1.5401x; 1.2459x over previous
#include <cuda_runtime.h>
#include <cuda_bf16.h>

// Problem constants (fixed by reference setup_inputs)
#define BATCH   16
#define NHEAD   16
#define HDIM    64
#define HW      4096                   // H*W
#define ROWQ    (HW / 4)               // float4s per row = 1024
#define NROWS   (BATCH * NHEAD * HDIM) // 16384 rows
#define LSEQ    16                     // sequence length (= nH)
#define BN      4                      // bottleneck dim
#define MHA_H   2
#define DH      2

#define GRID    1024                   // one block per (nH,hd) row slot
#define TPB     256

// Scratch + barrier state (no allocations allowed)
__device__ float    g_pooled[NROWS];
__device__ float    g_delta [NROWS];
__device__ unsigned g_cntA  = 0;       // pool-phase arrivals (all GRID blocks)
__device__ unsigned g_cntB  = 0;       // middle-phase arrivals (16 blocks)
__device__ unsigned g_epoch = 0;       // monotonic release counter (2 per replay)

__global__ __launch_bounds__(TPB, 7) void fused_kernel(
    const float* __restrict__ x,   float* __restrict__ out,
    const float* __restrict__ cw,  const float* __restrict__ cb,
    const float* __restrict__ ipw, const float* __restrict__ ipb,
    const float* __restrict__ opw, const float* __restrict__ opb,
    const float* __restrict__ ew,  const float* __restrict__ eb,
    const float* __restrict__ lnw, const float* __restrict__ lnb,
    const float* __restrict__ gate)
{
    const int bid = blockIdx.x;        // row within batch: nH*64 + hd
    const int t   = threadIdx.x;

    __shared__ float sp   [LSEQ * HDIM];
    __shared__ float s_xc [LSEQ][BN];
    __shared__ float s_qkv[LSEQ][3 * BN];
    __shared__ float s_sc [MHA_H * LSEQ][LSEQ];
    __shared__ float s_ov [LSEQ][BN];
    __shared__ float s_xat[LSEQ][BN];
    __shared__ float ws[2][8];          // paired pool reduction scratch
    __shared__ float wred[4][2];        // LN reduction scratch (4 groups)
    __shared__ unsigned s_e0;
    // weights (used only by blocks 0..15)
    __shared__ float s_cw [BN * HDIM], s_cb [BN];
    __shared__ float s_ipw[3 * BN * BN], s_ipb[3 * BN];
    __shared__ float s_opw[BN * BN],  s_opb[BN];
    __shared__ float s_ew [HDIM * BN], s_eb [HDIM];
    __shared__ float s_lnw[HDIM], s_lnb[HDIM];
    __shared__ float s_gate;

    if (t == 0) s_e0 = *(volatile unsigned*)&g_epoch;  // epoch at entry
    if (bid < BATCH) {                  // only middle blocks need weights
        if (t < BN * HDIM) s_cw[t] = cw[t];
        if (t < HDIM * BN) s_ew[t] = ew[t];
        if (t < 3 * BN * BN) s_ipw[t] = ipw[t];
        if (t < 3 * BN)      s_ipb[t] = ipb[t];
        if (t < BN * BN)     s_opw[t] = opw[t];
        if (t < BN)        { s_opb[t] = opb[t]; s_cb[t] = cb[t]; }
        if (t < HDIM)      { s_eb[t] = eb[t]; s_lnw[t] = lnw[t]; s_lnb[t] = lnb[t]; }
        if (t == 0)          s_gate = gate[0];
    }
    __syncthreads();
    const unsigned e0 = s_e0;

    const float4* __restrict__ x4 = reinterpret_cast<const float4*>(x);
    float4*       __restrict__ o4 = reinterpret_cast<float4*>(out);

    // ======== Phase 1: pool all 16 batches (paired, ascending) ==============
    for (int b = 0; b < BATCH; b += 2) {
        const size_t g0 = (size_t)b * (LSEQ * HDIM) + bid;
        const size_t g1 = g0 + (LSEQ * HDIM);
        const float4* __restrict__ xr0 = x4 + g0 * ROWQ;
        const float4* __restrict__ xr1 = x4 + g1 * ROWQ;

        float s0 = 0.f, s1 = 0.f;
#pragma unroll
        for (int i = 0; i < 4; i++) {     // 8 loads in flight
            float4 v0 = xr0[t + i * TPB];
            float4 v1 = xr1[t + i * TPB];
            s0 += (v0.x + v0.y) + (v0.z + v0.w);
            s1 += (v1.x + v1.y) + (v1.z + v1.w);
        }
#pragma unroll
        for (int off = 16; off; off >>= 1) {
            s0 += __shfl_xor_sync(0xffffffffu, s0, off);
            s1 += __shfl_xor_sync(0xffffffffu, s1, off);
        }
        if ((t & 31) == 0) { ws[0][t >> 5] = s0; ws[1][t >> 5] = s1; }
        __syncthreads();
        if (t == 0) {
            float t0 = 0.f, t1 = 0.f;
#pragma unroll
            for (int w = 0; w < 8; w++) { t0 += ws[0][w]; t1 += ws[1][w]; }
            g_pooled[g0] = t0 * (1.0f / (float)HW);
            g_pooled[g1] = t1 * (1.0f / (float)HW);
        }
        __syncthreads();
    }

    // arrive at barrier A
    if (t == 0) {
        __threadfence();
        unsigned old = atomicAdd(&g_cntA, 1u);
        if (old == GRID - 1) { g_cntA = 0; __threadfence(); atomicAdd(&g_epoch, 1u); }
    }

    // ======== Phase 2: blocks 0..15 compute one batch's middle each =========
    if (bid < BATCH) {
        if (t == 0) {
            while ((int)(*(volatile unsigned*)&g_epoch - (e0 + 1u)) < 0)
                __nanosleep(32);
            __threadfence();
        }
        __syncthreads();

        const int b = bid;
        const float* __restrict__ pb = g_pooled + (size_t)b * (LSEQ * HDIM);
#pragma unroll
        for (int i = 0; i < 4; i++)
            sp[t + i * TPB] = __ldcg(pb + t + i * TPB);
        __syncthreads();

        // compress: 64 outputs
        if (t < LSEQ * BN) {
            const int l = t >> 2, e = t & 3;
            float acc = s_cb[e];
#pragma unroll 8
            for (int k = 0; k < HDIM; k++)
                acc = fmaf(sp[l * HDIM + k], s_cw[e * HDIM + k], acc);
            s_xc[l][e] = acc;
        }
        __syncthreads();

        // qkv: 192 outputs
        if (t < LSEQ * 3 * BN) {
            const int l = t / (3 * BN), e = t % (3 * BN);
            float acc = s_ipb[e];
#pragma unroll
            for (int k = 0; k < BN; k++)
                acc = fmaf(s_xc[l][k], s_ipw[e * BN + k], acc);
            s_qkv[l][e] = acc;
        }
        __syncthreads();

        // attention: 2 heads x 16 queries
        if (t < MHA_H * LSEQ) {
            const int h = t / LSEQ, q = t % LSEQ;
            const float scale = rsqrtf((float)DH);
            const float q0 = s_qkv[q][h * DH + 0];
            const float q1 = s_qkv[q][h * DH + 1];
            float m = -1e30f;
#pragma unroll
            for (int k = 0; k < LSEQ; k++) {
                float sc = (q0 * s_qkv[k][BN + h * DH + 0] +
                            q1 * s_qkv[k][BN + h * DH + 1]) * scale;
                s_sc[t][k] = sc;
                m = fmaxf(m, sc);
            }
            float den = 0.f;
#pragma unroll
            for (int k = 0; k < LSEQ; k++) {
                float e2 = __expf(s_sc[t][k] - m);
                s_sc[t][k] = e2;
                den += e2;
            }
            const float inv = 1.0f / den;
            float o0 = 0.f, o1 = 0.f;
#pragma unroll
            for (int k = 0; k < LSEQ; k++) {
                const float a = s_sc[t][k] * inv;
                o0 = fmaf(a, s_qkv[k][2 * BN + h * DH + 0], o0);
                o1 = fmaf(a, s_qkv[k][2 * BN + h * DH + 1], o1);
            }
            s_ov[q][h * DH + 0] = o0;
            s_ov[q][h * DH + 1] = o1;
        }
        __syncthreads();

        // out_proj: 64 outputs
        if (t < LSEQ * BN) {
            const int l = t >> 2, e = t & 3;
            float acc = s_opb[e];
#pragma unroll
            for (int k = 0; k < BN; k++)
                acc = fmaf(s_ov[l][k], s_opw[e * BN + k], acc);
            s_xat[l][e] = acc;
        }
        __syncthreads();

        // expand + residual + gate + LN for all 16 l (4 groups of 64 per pass)
        const float g = s_gate;
        const int j = t & 63;
        const int grp = t >> 6;
#pragma unroll
        for (int pass = 0; pass < 4; pass++) {
            const int l = pass * 4 + grp;
            float xe = s_eb[j];
#pragma unroll
            for (int k = 0; k < BN; k++)
                xe = fmaf(s_xat[l][k], s_ew[j * BN + k], xe);
            const float res = sp[l * HDIM + j];
            const float y = fmaf(g, xe, res);

            float sm = y;
#pragma unroll
            for (int off = 16; off; off >>= 1)
                sm += __shfl_xor_sync(0xffffffffu, sm, off);
            if ((t & 31) == 0) wred[grp][(t >> 5) & 1] = sm;
            __syncthreads();
            const float mu = (wred[grp][0] + wred[grp][1]) * (1.0f / (float)HDIM);
            __syncthreads();

            const float dy = y - mu;
            float s2 = dy * dy;
#pragma unroll
            for (int off = 16; off; off >>= 1)
                s2 += __shfl_xor_sync(0xffffffffu, s2, off);
            if ((t & 31) == 0) wred[grp][(t >> 5) & 1] = s2;
            __syncthreads();
            const float var = (wred[grp][0] + wred[grp][1]) * (1.0f / (float)HDIM);

            const float ln = dy * rsqrtf(var + 1e-5f) * s_lnw[j] + s_lnb[j];
            g_delta[(size_t)b * (LSEQ * HDIM) + l * HDIM + j] = ln - res;
            __syncthreads();
        }

        if (t == 0) {
            __threadfence();
            unsigned old = atomicAdd(&g_cntB, 1u);
            if (old == BATCH - 1) { g_cntB = 0; __threadfence(); atomicAdd(&g_epoch, 1u); }
        }
    }

    // ======== barrier B: wait until all deltas are published ================
    if (t == 0) {
        while ((int)(*(volatile unsigned*)&g_epoch - (e0 + 2u)) < 0)
            __nanosleep(32);
        __threadfence();
    }
    __syncthreads();

    // ======== Phase 3: write out = x + delta, descending (L2-hot first) =====
    for (int b = BATCH - 1; b >= 1; b -= 2) {
        const size_t g0 = (size_t)b * (LSEQ * HDIM) + bid;        // hotter
        const size_t g1 = g0 - (LSEQ * HDIM);
        const float d0 = __ldcg(&g_delta[g0]);
        const float d1 = __ldcg(&g_delta[g1]);
        const float4* __restrict__ xr0 = x4 + g0 * ROWQ;
        const float4* __restrict__ xr1 = x4 + g1 * ROWQ;
        float4* __restrict__ or0 = o4 + g0 * ROWQ;
        float4* __restrict__ or1 = o4 + g1 * ROWQ;

#pragma unroll
        for (int i = 0; i < 4; i++) {
            float4 v0 = __ldcs(xr0 + t + i * TPB);
            float4 v1 = __ldcs(xr1 + t + i * TPB);
            v0.x += d0; v0.y += d0; v0.z += d0; v0.w += d0;
            v1.x += d1; v1.y += d1; v1.z += d1; v1.w += d1;
            __stcs(or0 + t + i * TPB, v0);
            __stcs(or1 + t + i * TPB, v1);
        }
    }
}

// ---------------------------------------------------------------------------
extern "C" void kernel_launch(void* const* d_in, const int* in_sizes, int n_in,
                              void* d_out, int out_size) {
    const float* x   = (const float*)d_in[0];
    const float* cw  = (const float*)d_in[1];
    const float* cb  = (const float*)d_in[2];
    const float* ipw = (const float*)d_in[3];
    const float* ipb = (const float*)d_in[4];
    const float* opw = (const float*)d_in[5];
    const float* opb = (const float*)d_in[6];
    const float* ew  = (const float*)d_in[7];
    const float* eb  = (const float*)d_in[8];
    const float* lnw = (const float*)d_in[9];
    const float* lnb = (const float*)d_in[10];
    const float* gt  = (const float*)d_in[11];
    float* out = (float*)d_out;

    fused_kernel<<<GRID, TPB>>>(x, out, cw, cb, ipw, ipb, opw, opb,
                                ew, eb, lnw, lnb, gt);
}